// round 8
// baseline (speedup 1.0000x reference)
#include <cuda_runtime.h>
#include <cuda_bf16.h>

// RippleNet: H=2, B=2048, M=64, D=16, N_ENT=500000, N_REL=32
// inputs: items[B] i32, heads[H,B,M] i32, relations[H,B,M] i32,
//         tails[H,B,M] i32, ent_emb[N_ENT,16] f32, rel_emb[32,16,16] f32
// output: predicts[B] f32

#define H_ 2
#define B_ 2048
#define M_ 64
#define D_ 16
#define NREL_ 32
#define QS 20   // q row stride in floats: float4-aligned, low bank conflict

// 2 items per CTA, 256 threads. Sub-block of 128 threads per item b;
// within a sub-block: quad (4 lanes) = one 64B entity row, thread owns rows
// {quad, quad+32, quad+64, quad+96} chunk ch (identical to the proven R4 map).
// Shared rel pass: warps 0-3 compute q for BOTH items in one sweep.
__global__ __launch_bounds__(256, 4) void ripple_kernel(
    const int* __restrict__ items,
    const int* __restrict__ heads,
    const int* __restrict__ rels,
    const int* __restrict__ tails,
    const float* __restrict__ ent,
    const float* __restrict__ rel,
    float* __restrict__ out)
{
    const int tid  = threadIdx.x;      // 0..255
    const int sub  = tid >> 7;         // which item (0/1)
    const int lt   = tid & 127;
    const int quad = lt >> 2;
    const int ch   = lt & 3;
    const int j0   = ch * 4;
    const int b0   = blockIdx.x * 2;

    __shared__ float item_s[2][D_];           // item embeddings (float4-aligned)
    __shared__ int   idx_s[3][2][128];        // [head|rel|tail][sub][row]
    __shared__ float q[2][NREL_ * QS];
    __shared__ float4 wsum[8];                // per-warp {se0,ses0,se1,ses1}

    // ---- cooperative coalesced index staging: 192 int4 loads total ----
    if (tid < 192) {
        const int a   = tid / 64;             // 0=head,1=rel,2=tail
        const int rem = tid - a * 64;
        const int sb  = rem >> 5;             // item sub
        const int hop = (rem >> 4) & 1;
        const int i4  = rem & 15;             // int4 index within 64-int segment
        const int* src = (a == 0 ? heads : (a == 1 ? rels : tails))
                       + hop * (B_ * M_) + (b0 + sb) * M_ + i4 * 4;
        *(int4*)&idx_s[a][sb][hop * 64 + i4 * 4] = *(const int4*)src;
    }
    // item embeddings: 2 rows
    if (tid < 32) {
        const int sb = tid >> 4, j = tid & 15;
        item_s[sb][j] = ent[(size_t)items[b0 + sb] * D_ + j];
    }
    __syncthreads();

    // ---- per-thread indices from smem (quad-broadcast LDS) ----
    int hidx[4], ridx[4], tidx[4];
    #pragma unroll
    for (int k = 0; k < 4; k++) {
        const int row = quad + 32 * k;        // 0..127 (rows 0-63 hop0, 64-127 hop1)
        hidx[k] = idx_s[0][sub][row];
        ridx[k] = idx_s[1][sub][row];
        tidx[k] = idx_s[2][sub][row];
    }

    // ---- front-batch all embedding gathers (quad-coalesced, MLP=8) ----
    float4 hv[4], tv[4];
    #pragma unroll
    for (int k = 0; k < 4; k++)
        hv[k] = *(const float4*)(ent + (size_t)hidx[k] * D_ + j0);
    #pragma unroll
    for (int k = 0; k < 4; k++)
        tv[k] = *(const float4*)(ent + (size_t)tidx[k] * D_ + j0);
    const float4 vi = *(const float4*)&item_s[sub][j0];

    // ---- q for BOTH items in ONE rel sweep (warps 0-3 only) ----
    if (tid < 128) {
        const int r = tid >> 2, c = tid & 3;
        const float4* Rp = (const float4*)(rel + r * (D_ * D_)) + c;
        float4 a0 = make_float4(0.f, 0.f, 0.f, 0.f);
        float4 a1 = make_float4(0.f, 0.f, 0.f, 0.f);
        #pragma unroll
        for (int i = 0; i < D_; i++) {
            const float4 rv = Rp[i * 4];
            const float w0 = item_s[0][i];
            const float w1 = item_s[1][i];
            a0.x = fmaf(w0, rv.x, a0.x); a0.y = fmaf(w0, rv.y, a0.y);
            a0.z = fmaf(w0, rv.z, a0.z); a0.w = fmaf(w0, rv.w, a0.w);
            a1.x = fmaf(w1, rv.x, a1.x); a1.y = fmaf(w1, rv.y, a1.y);
            a1.z = fmaf(w1, rv.z, a1.z); a1.w = fmaf(w1, rv.w, a1.w);
        }
        *(float4*)&q[0][r * QS + c * 4] = a0;
        *(float4*)&q[1][r * QS + c * 4] = a1;
    }

    // ---- tail dots (independent of q; tv dies early) ----
    float s[4];
    #pragma unroll
    for (int k = 0; k < 4; k++) {
        float ps = fmaf(vi.x, tv[k].x, fmaf(vi.y, tv[k].y,
                   fmaf(vi.z, tv[k].z, vi.w * tv[k].w)));
        ps += __shfl_xor_sync(0xffffffffu, ps, 1);
        ps += __shfl_xor_sync(0xffffffffu, ps, 2);
        s[k] = ps;
    }

    __syncthreads();   // q ready

    // ---- head dots: logit via q[sub][ridx] (LDS.128) ----
    float l[4];
    #pragma unroll
    for (int k = 0; k < 4; k++) {
        const float4 w = *(const float4*)&q[sub][ridx[k] * QS + j0];
        float p = fmaf(w.x, hv[k].x, fmaf(w.y, hv[k].y,
                  fmaf(w.z, hv[k].z, w.w * hv[k].w)));
        p += __shfl_xor_sync(0xffffffffu, p, 1);
        p += __shfl_xor_sync(0xffffffffu, p, 2);
        l[k] = p;
    }

    // ---- softmax w/o max subtraction (|l| ~ 0.1; exp safe, identical math) ----
    const float e0 = __expf(l[0]), e1 = __expf(l[1]);
    const float e2 = __expf(l[2]), e3 = __expf(l[3]);
    float se0  = e0 + e1;
    float ses0 = fmaf(e0, s[0], e1 * s[1]);
    float se1  = e2 + e3;
    float ses1 = fmaf(e2, s[2], e3 * s[3]);

    // lanes within a quad hold identical values -> reduce offsets 16,8,4 only
    #pragma unroll
    for (int off = 16; off >= 4; off >>= 1) {
        se0  += __shfl_xor_sync(0xffffffffu, se0,  off);
        ses0 += __shfl_xor_sync(0xffffffffu, ses0, off);
        se1  += __shfl_xor_sync(0xffffffffu, se1,  off);
        ses1 += __shfl_xor_sync(0xffffffffu, ses1, off);
    }
    if ((tid & 31) == 0)
        wsum[tid >> 5] = make_float4(se0, ses0, se1, ses1);
    __syncthreads();

    if (lt == 0) {    // tid 0 -> b0, tid 128 -> b0+1
        float SE0 = 0.f, SES0 = 0.f, SE1 = 0.f, SES1 = 0.f;
        #pragma unroll
        for (int i = 0; i < 4; i++) {
            const float4 v = wsum[sub * 4 + i];
            SE0 += v.x; SES0 += v.y; SE1 += v.z; SES1 += v.w;
        }
        // 4x quad-lane replication cancels in each ratio
        const float x = SES0 / SE0 + SES1 / SE1;
        out[b0 + sub] = 1.f / (1.f + __expf(-x));
    }
}

extern "C" void kernel_launch(void* const* d_in, const int* in_sizes, int n_in,
                              void* d_out, int out_size) {
    const int*   items = (const int*)  d_in[0];
    const int*   heads = (const int*)  d_in[1];
    const int*   rels  = (const int*)  d_in[2];
    const int*   tails = (const int*)  d_in[3];
    const float* ent   = (const float*)d_in[4];
    const float* rel   = (const float*)d_in[5];
    float* out = (float*)d_out;

    ripple_kernel<<<B_ / 2, 256>>>(items, heads, rels, tails, ent, rel, out);
}

// round 9
// speedup vs baseline: 1.1830x; 1.1830x over previous
#include <cuda_runtime.h>
#include <cuda_bf16.h>

// RippleNet: H=2, B=2048, M=64, D=16, N_ENT=500000, N_REL=32
// inputs: items[B] i32, heads[H,B,M] i32, relations[H,B,M] i32,
//         tails[H,B,M] i32, ent_emb[N_ENT,16] f32, rel_emb[32,16,16] f32
// output: predicts[B] f32

#define H_ 2
#define B_ 2048
#define M_ 64
#define D_ 16
#define NREL_ 32
#define QS 20   // q row stride in floats: float4-aligned, low bank conflict

// One block per b, 128 threads (R4 shape — proven best latency structure).
// Gathers: quad (4 lanes) = one 64B entity row; thread (quad,ch) owns rows
// {quad, quad+32, quad+64, quad+96}, 16B chunk ch.
// q-phase: octet (8 lanes) = one rel; per instruction each octet touches one
// full 128B line (rows 2k, 2k+1) -> 4 wf/instr instead of 8, 64 wf total.
__global__ __launch_bounds__(128, 8) void ripple_kernel(
    const int* __restrict__ items,
    const int* __restrict__ heads,
    const int* __restrict__ rels,
    const int* __restrict__ tails,
    const float* __restrict__ ent,
    const float* __restrict__ rel,
    float* __restrict__ out)
{
    const int b    = blockIdx.x;
    const int tid  = threadIdx.x;
    const int quad = tid >> 2;
    const int ch   = tid & 3;
    const int j0   = ch * 4;

    __shared__ float  item_s[D_];
    __shared__ float  q[NREL_ * QS];
    __shared__ float4 wsum[4];        // per-warp {se0, ses0, se1, ses1}

    const int it = items[b];
    if (tid < D_) item_s[tid] = __ldg(ent + (size_t)it * D_ + tid);

    // ---- index loads (quad-broadcast, 1 wf/instr) ----
    int hidx[4], ridx[4], tidx[4];
    #pragma unroll
    for (int k = 0; k < 4; k++) {
        const int row  = quad + 32 * k;
        const int base = (row >> 6) * (B_ * M_) + b * M_ + (row & 63);
        hidx[k] = __ldg(heads + base);
        ridx[k] = __ldg(rels  + base);
        tidx[k] = __ldg(tails + base);
    }

    // ---- front-batch all embedding gathers (quad-coalesced, high MLP) ----
    const float4 vi = __ldg((const float4*)(ent + (size_t)it * D_ + j0));
    float4 hv[4], tv[4];
    #pragma unroll
    for (int k = 0; k < 4; k++)
        hv[k] = __ldg((const float4*)(ent + (size_t)hidx[k] * D_ + j0));
    #pragma unroll
    for (int k = 0; k < 4; k++)
        tv[k] = __ldg((const float4*)(ent + (size_t)tidx[k] * D_ + j0));

    __syncthreads();   // item_s ready; in-flight gathers keep flying

    // ---- q-phase, octet-coalesced: lane (ch,half) of octet O covers rel r,
    //      rows i = 2k + half. One 128B line per octet per step. ----
    {
        const int lane = tid & 31;
        const int O    = (tid >> 5) * 4 + ((lane >> 3) & 3);   // global octet 0..15
        const int half = (lane >> 2) & 1;

        #pragma unroll
        for (int rr = 0; rr < 2; rr++) {
            const int r = O + 16 * rr;                          // rels O, O+16
            const float4* Rp = (const float4*)(rel + r * (D_ * D_)) + ch;
            float4 acc = make_float4(0.f, 0.f, 0.f, 0.f);
            #pragma unroll
            for (int k = 0; k < 8; k++) {
                const int i = 2 * k + half;
                const float4 rv = Rp[i * 4];
                const float  wi = item_s[i];
                acc.x = fmaf(wi, rv.x, acc.x);
                acc.y = fmaf(wi, rv.y, acc.y);
                acc.z = fmaf(wi, rv.z, acc.z);
                acc.w = fmaf(wi, rv.w, acc.w);
            }
            // merge even/odd halves within the octet
            acc.x += __shfl_xor_sync(0xffffffffu, acc.x, 4);
            acc.y += __shfl_xor_sync(0xffffffffu, acc.y, 4);
            acc.z += __shfl_xor_sync(0xffffffffu, acc.z, 4);
            acc.w += __shfl_xor_sync(0xffffffffu, acc.w, 4);
            if (half == 0)
                *(float4*)&q[r * QS + j0] = acc;
        }
    }

    // ---- tail dots (independent of q; tv dies early) ----
    float s[4];
    #pragma unroll
    for (int k = 0; k < 4; k++) {
        float ps = fmaf(vi.x, tv[k].x, fmaf(vi.y, tv[k].y,
                   fmaf(vi.z, tv[k].z, vi.w * tv[k].w)));
        ps += __shfl_xor_sync(0xffffffffu, ps, 1);
        ps += __shfl_xor_sync(0xffffffffu, ps, 2);
        s[k] = ps;
    }

    __syncthreads();   // q ready

    // ---- head dots: logit via q[ridx] (LDS.128) ----
    float l[4];
    #pragma unroll
    for (int k = 0; k < 4; k++) {
        const float4 w = *(const float4*)&q[ridx[k] * QS + j0];
        float p = fmaf(w.x, hv[k].x, fmaf(w.y, hv[k].y,
                  fmaf(w.z, hv[k].z, w.w * hv[k].w)));
        p += __shfl_xor_sync(0xffffffffu, p, 1);
        p += __shfl_xor_sync(0xffffffffu, p, 2);
        l[k] = p;
    }

    // ---- softmax w/o max subtraction (|l| ~ 0.1; exp safe, identical math) ----
    const float e0 = __expf(l[0]), e1 = __expf(l[1]);
    const float e2 = __expf(l[2]), e3 = __expf(l[3]);
    float se0  = e0 + e1;
    float ses0 = fmaf(e0, s[0], e1 * s[1]);
    float se1  = e2 + e3;
    float ses1 = fmaf(e2, s[2], e3 * s[3]);

    // lanes within a quad hold identical values -> reduce offsets 16,8,4 only
    #pragma unroll
    for (int off = 16; off >= 4; off >>= 1) {
        se0  += __shfl_xor_sync(0xffffffffu, se0,  off);
        ses0 += __shfl_xor_sync(0xffffffffu, ses0, off);
        se1  += __shfl_xor_sync(0xffffffffu, se1,  off);
        ses1 += __shfl_xor_sync(0xffffffffu, ses1, off);
    }
    if ((tid & 31) == 0)
        wsum[tid >> 5] = make_float4(se0, ses0, se1, ses1);
    __syncthreads();

    if (tid == 0) {
        float SE0 = 0.f, SES0 = 0.f, SE1 = 0.f, SES1 = 0.f;
        #pragma unroll
        for (int i = 0; i < 4; i++) {
            const float4 v = wsum[i];
            SE0 += v.x; SES0 += v.y; SE1 += v.z; SES1 += v.w;
        }
        // 4x quad-lane replication cancels in each ratio
        const float x = SES0 / SE0 + SES1 / SE1;
        out[b] = 1.f / (1.f + __expf(-x));
    }
}

extern "C" void kernel_launch(void* const* d_in, const int* in_sizes, int n_in,
                              void* d_out, int out_size) {
    const int*   items = (const int*)  d_in[0];
    const int*   heads = (const int*)  d_in[1];
    const int*   rels  = (const int*)  d_in[2];
    const int*   tails = (const int*)  d_in[3];
    const float* ent   = (const float*)d_in[4];
    const float* rel   = (const float*)d_in[5];
    float* out = (float*)d_out;

    ripple_kernel<<<B_, 128>>>(items, heads, rels, tails, ent, rel, out);
}